// round 1
// baseline (speedup 1.0000x reference)
#include <cuda_runtime.h>

#define D  512
#define DD (D * D)

// Scratch ping-pong buffers (static __device__ per allocation rules).
// Level 1 writes 500 matrices -> b0 (500 MB-class), level 2 writes 250 -> b1.
__device__ float g_buf0[500 * DD];
__device__ float g_buf1[250 * DD];

// C_p = in[2p+1] @ in[2p]   (all 512x512 row-major fp32)
// If FIRST, 'in' is the raw A stack and each element is transformed on load:
//   M[i][k] = (i==k ? 1 : 0) - A[i][k] / 1000
template <bool FIRST>
__global__ __launch_bounds__(256, 2)
void pair_gemm(const float* __restrict__ in, float* __restrict__ out)
{
    __shared__ float sL[8][128];   // transposed: sL[k][m]
    __shared__ float sR[8][128];   // sR[k][n]

    const int p = blockIdx.z;
    const float* __restrict__ L = in + (size_t)(2 * p + 1) * DD;
    const float* __restrict__ R = in + (size_t)(2 * p) * DD;
    float* __restrict__ C = out + (size_t)p * DD;

    const int tid = threadIdx.x;
    const int tr  = tid >> 4;          // 0..15
    const int tc  = tid & 15;          // 0..15
    const int bm  = blockIdx.y * 128;
    const int bn  = blockIdx.x * 128;

    // Global-load assignments (one float4 per thread per tile)
    const int lrow = tid >> 1;          // 0..127
    const int lk4  = (tid & 1) * 4;     // 0 or 4
    const int rrow = tid >> 5;          // 0..7
    const int rc4  = (tid & 31) * 4;    // 0..124

    float acc[8][8];
    #pragma unroll
    for (int i = 0; i < 8; i++)
        #pragma unroll
        for (int j = 0; j < 8; j++)
            acc[i][j] = 0.0f;

    const float s = -(1.0f / 1000.0f);

    for (int k0 = 0; k0 < D; k0 += 8) {
        float4 lv = *(const float4*)(L + (size_t)(bm + lrow) * D + (k0 + lk4));
        float4 rv = *(const float4*)(R + (size_t)(k0 + rrow) * D + (bn + rc4));

        if (FIRST) {
            const int gr = bm + lrow, gc = k0 + lk4;
            lv.x = lv.x * s + ((gr == gc + 0) ? 1.0f : 0.0f);
            lv.y = lv.y * s + ((gr == gc + 1) ? 1.0f : 0.0f);
            lv.z = lv.z * s + ((gr == gc + 2) ? 1.0f : 0.0f);
            lv.w = lv.w * s + ((gr == gc + 3) ? 1.0f : 0.0f);
            const int rr = k0 + rrow, rcc = bn + rc4;
            rv.x = rv.x * s + ((rr == rcc + 0) ? 1.0f : 0.0f);
            rv.y = rv.y * s + ((rr == rcc + 1) ? 1.0f : 0.0f);
            rv.z = rv.z * s + ((rr == rcc + 2) ? 1.0f : 0.0f);
            rv.w = rv.w * s + ((rr == rcc + 3) ? 1.0f : 0.0f);
        }

        sL[lk4 + 0][lrow] = lv.x;
        sL[lk4 + 1][lrow] = lv.y;
        sL[lk4 + 2][lrow] = lv.z;
        sL[lk4 + 3][lrow] = lv.w;
        *(float4*)&sR[rrow][rc4] = rv;
        __syncthreads();

        #pragma unroll
        for (int k = 0; k < 8; ++k) {
            float a[8], b[8];
            *(float4*)&a[0] = *(const float4*)&sL[k][tr * 8];
            *(float4*)&a[4] = *(const float4*)&sL[k][tr * 8 + 4];
            *(float4*)&b[0] = *(const float4*)&sR[k][tc * 8];
            *(float4*)&b[4] = *(const float4*)&sR[k][tc * 8 + 4];
            #pragma unroll
            for (int i = 0; i < 8; i++)
                #pragma unroll
                for (int j = 0; j < 8; j++)
                    acc[i][j] += a[i] * b[j];
        }
        __syncthreads();
    }

    #pragma unroll
    for (int i = 0; i < 8; i++) {
        float* crow = C + (size_t)(bm + tr * 8 + i) * D + (bn + tc * 8);
        *(float4*)(crow + 0) = make_float4(acc[i][0], acc[i][1], acc[i][2], acc[i][3]);
        *(float4*)(crow + 4) = make_float4(acc[i][4], acc[i][5], acc[i][6], acc[i][7]);
    }
}

extern "C" void kernel_launch(void* const* d_in, const int* in_sizes, int n_in,
                              void* d_out, int out_size)
{
    (void)in_sizes; (void)n_in; (void)out_size;
    const float* A = (const float*)d_in[0];
    float* out = (float*)d_out;

    float *b0 = nullptr, *b1 = nullptr;
    cudaGetSymbolAddress((void**)&b0, g_buf0);
    cudaGetSymbolAddress((void**)&b1, g_buf1);

    // Level 1: 1000 raw A matrices -> 500 pair products (M formed on load)
    pair_gemm<true><<<dim3(4, 4, 500), 256>>>(A, b0);

    // Remaining tree levels: 500 -> 250 -> 125 -> 63 -> 32 -> 16 -> 8 -> 4 -> 2 -> 1
    int cnt = 500;
    float* src = b0;
    float* dst = b1;
    while (cnt > 1) {
        const int pairs = cnt >> 1;
        float* o = (cnt == 2) ? out : dst;
        pair_gemm<false><<<dim3(4, 4, pairs), 256>>>(src, o);
        if (cnt & 1) {
            // odd count: last matrix passes through unchanged
            cudaMemcpyAsync(o + (size_t)pairs * DD,
                            src + (size_t)(cnt - 1) * DD,
                            DD * sizeof(float), cudaMemcpyDeviceToDevice);
        }
        cnt = pairs + (cnt & 1);
        float* t = src; src = dst; dst = t;
    }
}

// round 4
// speedup vs baseline: 4.6763x; 4.6763x over previous
#include <cuda_runtime.h>
#include <cuda_bf16.h>
#include <cstdint>

#define D  512
#define DD (D * D)

// tcgen05 exists only in the arch-specific target; stub out the plain
// compute_103/sm_103 gencode pass (never selected on the sm_103a device).
#if !defined(__CUDA_ARCH__) || defined(__CUDA_ARCH_FEAT_SM103_ALL) || defined(__CUDA_ARCH_FEAT_SM100_ALL)
#define HAS_TCGEN05 1
#endif

// fp32 intermediate ping-pong buffers
__device__ float g_buf0[500 * DD];
__device__ float g_buf1[250 * DD];

// ---------------- PTX helpers ----------------
__device__ __forceinline__ uint32_t smem_u32(const void* p) {
    uint32_t a;
    asm("{ .reg .u64 t; cvta.to.shared.u64 t, %1; cvt.u32.u64 %0, t; }" : "=r"(a) : "l"(p));
    return a;
}
__device__ __forceinline__ uint32_t elect_one() {
    uint32_t p;
    asm volatile("{ .reg .pred p; elect.sync _|p, 0xFFFFFFFF; selp.b32 %0,1,0,p; }" : "=r"(p));
    return p;
}
__device__ __forceinline__ void mbar_wait(uint32_t addr, uint32_t parity) {
    asm volatile(
        "{\n\t.reg .pred P;\n\t"
        "WL_%=:\n\t"
        "mbarrier.try_wait.parity.acquire.cta.shared::cta.b64 P, [%0], %1, 0x989680;\n\t"
        "@!P bra WL_%=;\n\t}"
        :: "r"(addr), "r"(parity) : "memory");
}
// K-major SW128 descriptor (LBO=1, SBO=64), 128-byte rows — validated config.
__device__ __forceinline__ uint64_t desc_k(uint32_t addr) {
    return ((uint64_t)2 << 61) | ((uint64_t)1 << 46) | ((uint64_t)64 << 32) |
           ((uint64_t)1 << 16) | ((addr >> 4) & 0x3FFF);
}
// idesc: f32 accum (bit4), bf16 A (bit7), bf16 B (bit10), N=128 (16<<17),
// M=128 (8<<24). Both operands K-major — no transpose bits.
#define IDESC 0x8200490u

#ifdef HAS_TCGEN05
__device__ __forceinline__ void mma_bf16(uint32_t d, uint64_t a, uint64_t b, uint32_t en) {
    asm volatile(
        "{\n\t.reg .pred p;\n\tsetp.ne.u32 p, %5, 0;\n\t"
        "tcgen05.mma.cta_group::1.kind::f16 [%0], %1, %2, %3, {%4,%4,%4,%4}, p;\n\t}"
        :: "r"(d), "l"(a), "l"(b), "r"(IDESC), "r"(0u), "r"(en) : "memory");
}
#define LDTM_X32(r, addr)                                                        \
    asm volatile(                                                                \
        "tcgen05.ld.sync.aligned.32x32b.x32.b32 "                                \
        "{%0,%1,%2,%3,%4,%5,%6,%7,%8,%9,%10,%11,%12,%13,%14,%15,"                \
        "%16,%17,%18,%19,%20,%21,%22,%23,%24,%25,%26,%27,%28,%29,%30,%31},[%32];"\
        : "=r"((r)[0]), "=r"((r)[1]), "=r"((r)[2]), "=r"((r)[3]),                \
          "=r"((r)[4]), "=r"((r)[5]), "=r"((r)[6]), "=r"((r)[7]),                \
          "=r"((r)[8]), "=r"((r)[9]), "=r"((r)[10]), "=r"((r)[11]),              \
          "=r"((r)[12]), "=r"((r)[13]), "=r"((r)[14]), "=r"((r)[15]),            \
          "=r"((r)[16]), "=r"((r)[17]), "=r"((r)[18]), "=r"((r)[19]),            \
          "=r"((r)[20]), "=r"((r)[21]), "=r"((r)[22]), "=r"((r)[23]),            \
          "=r"((r)[24]), "=r"((r)[25]), "=r"((r)[26]), "=r"((r)[27]),            \
          "=r"((r)[28]), "=r"((r)[29]), "=r"((r)[30]), "=r"((r)[31])             \
        : "r"(addr))
#endif

// pack two f32 -> bf16x2 (a -> low half, b -> high half)
__device__ __forceinline__ uint32_t pack_bf2(float a, float b) {
    uint32_t r;
    asm("cvt.rn.bf16x2.f32 %0, %1, %2;" : "=r"(r) : "f"(b), "f"(a));
    return r;
}
// hi/lo split of a pair: h = bf16x2(a,b); l = bf16x2(a-hi(a), b-hi(b))
__device__ __forceinline__ void split_pair(float a, float b, uint32_t& h, uint32_t& l) {
    h = pack_bf2(a, b);
    float ha = __uint_as_float(h << 16);
    float hb = __uint_as_float(h & 0xffff0000u);
    l = pack_bf2(a - ha, b - hb);
}

// smem layout (bytes)
#define SM_TMEMP 0
#define SM_MBAR  8
#define SM_LH    1024
#define SM_LL    (SM_LH + 16384)
#define SM_BH    (SM_LL + 16384)
#define SM_BL    (SM_BH + 16384)
#define SM_SCR   (SM_BL + 16384)        // fp32 scratch 64 x 128 = 32 KB
#define SM_TOTAL (SM_SCR + 32768)       // 99328

// C_p = M[2p+1] @ M[2p], 512x512 fp32.  FIRST: form M = I - A/1000 on load.
template <bool FIRST>
__global__ void __launch_bounds__(256, 2) tree_gemm(const float* __restrict__ in,
                                                    float* __restrict__ out)
{
#ifndef HAS_TCGEN05
    __trap();
#else
    extern __shared__ char smem[];
    const uint32_t sb = smem_u32(smem);
    const int tid = threadIdx.x;
    const int wid = tid >> 5, lid = tid & 31;
    const int p = blockIdx.z;
    const float* __restrict__ L = in + (size_t)(2 * p + 1) * DD;
    const float* __restrict__ R = in + (size_t)(2 * p) * DD;
    float* __restrict__ C = out + (size_t)p * DD;
    const int bm = blockIdx.y * 128, bn = blockIdx.x * 128;

    if (wid == 0) {
        asm volatile("tcgen05.alloc.cta_group::1.sync.aligned.shared::cta.b32 [%0], %1;"
                     :: "r"(sb + SM_TMEMP), "r"(128u) : "memory");
        asm volatile("tcgen05.relinquish_alloc_permit.cta_group::1.sync.aligned;");
    }
    if (tid == 0) {
        asm volatile("mbarrier.init.shared.b64 [%0], %1;" :: "r"(sb + SM_MBAR), "r"(1u) : "memory");
    }
    __syncthreads();
    uint32_t tmem;
    asm volatile("ld.shared.b32 %0,[%1];" : "=r"(tmem) : "r"(sb + SM_TMEMP));

    // LDG assignments
    const int lm  = tid >> 4;         // L row base (0..15): rows lm + 16*i
    const int lk4 = (tid & 15) * 4;   // L k-col within chunk (0..60)
    const int rk  = tid >> 5;         // R k-row base (0..7): rows rk + 8*i
    const int rn4 = (tid & 31) * 4;   // R n-col (0..124)

    // column-phase assignments (R transpose)
    const int cn  = tid & 127;        // B row index n (0..127)
    const int ck0 = (tid >> 7) * 32;  // k base: 0 or 32
    const uint32_t swx = (uint32_t)((cn & 7) << 4);

    float4 lreg[8], rreg[8];
    {
        const float* Lp = L + (size_t)(bm + lm) * D + lk4;
        const float* Rp = R + (size_t)rk * D + bn + rn4;
        #pragma unroll
        for (int i = 0; i < 8; i++) {
            lreg[i] = *(const float4*)(Lp + (size_t)16 * i * D);
            rreg[i] = *(const float4*)(Rp + (size_t)8 * i * D);
        }
    }

    for (int c = 0; c < 8; c++) {
        // stage R chunk (fp32, with FIRST transform) into scratch — not read
        // by MMA, safe before the mbarrier wait.
        #pragma unroll
        for (int i = 0; i < 8; i++) {
            float4 v = rreg[i];
            const int kk = rk + 8 * i;
            if (FIRST) {
                const int gr = c * 64 + kk, gc = bn + rn4;
                v.x = fmaf(v.x, -1e-3f, (gr == gc + 0) ? 1.f : 0.f);
                v.y = fmaf(v.y, -1e-3f, (gr == gc + 1) ? 1.f : 0.f);
                v.z = fmaf(v.z, -1e-3f, (gr == gc + 2) ? 1.f : 0.f);
                v.w = fmaf(v.w, -1e-3f, (gr == gc + 3) ? 1.f : 0.f);
            }
            *(float4*)(smem + SM_SCR + (size_t)kk * 512 + (size_t)rn4 * 4) = v;
        }

        if (c > 0) mbar_wait(sb + SM_MBAR, (uint32_t)((c - 1) & 1));

        // L: split + swizzled K-major store (A operand)
        #pragma unroll
        for (int i = 0; i < 8; i++) {
            float4 v = lreg[i];
            const int m = lm + 16 * i;
            if (FIRST) {
                const int gr = bm + m, gc = c * 64 + lk4;
                v.x = fmaf(v.x, -1e-3f, (gr == gc + 0) ? 1.f : 0.f);
                v.y = fmaf(v.y, -1e-3f, (gr == gc + 1) ? 1.f : 0.f);
                v.z = fmaf(v.z, -1e-3f, (gr == gc + 2) ? 1.f : 0.f);
                v.w = fmaf(v.w, -1e-3f, (gr == gc + 3) ? 1.f : 0.f);
            }
            uint32_t h0, l0, h1, l1;
            split_pair(v.x, v.y, h0, l0);
            split_pair(v.z, v.w, h1, l1);
            uint32_t off = (uint32_t)(m * 128 + lk4 * 2);
            off ^= (off >> 3) & 0x70;
            *(uint2*)(smem + SM_LH + off) = make_uint2(h0, h1);
            *(uint2*)(smem + SM_LL + off) = make_uint2(l0, l1);
        }
        __syncthreads();   // scratch + L visible; MMA(c-1) done for all

        // R transpose: read columns of scratch, split, store K-major B tile
        {
            const float* scr = (const float*)(smem + SM_SCR);
            #pragma unroll
            for (int j = 0; j < 4; j++) {
                const int kb = ck0 + 8 * j;
                float f[8];
                #pragma unroll
                for (int i = 0; i < 8; i++) f[i] = scr[(kb + i) * 128 + cn];
                uint32_t h[4], l[4];
                #pragma unroll
                for (int q = 0; q < 4; q++)
                    split_pair(f[2 * q], f[2 * q + 1], h[q], l[q]);
                const uint32_t off = (uint32_t)(cn * 128) + (((uint32_t)(kb * 2)) ^ swx);
                *(uint4*)(smem + SM_BH + off) = make_uint4(h[0], h[1], h[2], h[3]);
                *(uint4*)(smem + SM_BL + off) = make_uint4(l[0], l[1], l[2], l[3]);
            }
        }
        __syncthreads();

        if (wid == 0) {
            asm volatile("fence.proxy.async.shared::cta;" ::: "memory");
            if (elect_one()) {
                const uint64_t ah = desc_k(sb + SM_LH);
                const uint64_t al = desc_k(sb + SM_LL);
                const uint64_t bh = desc_k(sb + SM_BH);
                const uint64_t bl = desc_k(sb + SM_BL);
                #pragma unroll
                for (int ks = 0; ks < 4; ks++)
                    mma_bf16(tmem, ah + ks * 2, bh + ks * 2, (c == 0 && ks == 0) ? 0u : 1u);
                #pragma unroll
                for (int ks = 0; ks < 4; ks++)
                    mma_bf16(tmem, ah + ks * 2, bl + ks * 2, 1u);
                #pragma unroll
                for (int ks = 0; ks < 4; ks++)
                    mma_bf16(tmem, al + ks * 2, bh + ks * 2, 1u);
                asm volatile(
                    "tcgen05.commit.cta_group::1.mbarrier::arrive::one.shared::cluster.b64 [%0];"
                    :: "r"(sb + SM_MBAR) : "memory");
            }
        }

        // prefetch next chunk (overlaps MMA)
        if (c < 7) {
            const float* Lp = L + (size_t)(bm + lm) * D + (c + 1) * 64 + lk4;
            const float* Rp = R + (size_t)((c + 1) * 64 + rk) * D + bn + rn4;
            #pragma unroll
            for (int i = 0; i < 8; i++) {
                lreg[i] = *(const float4*)(Lp + (size_t)16 * i * D);
                rreg[i] = *(const float4*)(Rp + (size_t)8 * i * D);
            }
        }
    }
    mbar_wait(sb + SM_MBAR, 1u);  // completion 7 (parity 7&1)
    asm volatile("tcgen05.fence::after_thread_sync;" ::: "memory");

    // epilogue: warp wid reads rows (wid&3)*32, cols 0-63 (wid<4) / 64-127
    {
        uint32_t r0[32], r1[32];
        const uint32_t base = tmem + ((wid >= 4) ? 64u : 0u);
        LDTM_X32(r0, base);
        LDTM_X32(r1, base + 32);
        asm volatile("tcgen05.wait::ld.sync.aligned;" ::: "memory");

        const int row  = bm + (wid & 3) * 32 + lid;
        const int colb = bn + ((wid >= 4) ? 64 : 0);
        float* cp = C + (size_t)row * D + colb;
        #pragma unroll
        for (int j = 0; j < 32; j += 4)
            *(float4*)(cp + j) = make_float4(
                __uint_as_float(r0[j]), __uint_as_float(r0[j + 1]),
                __uint_as_float(r0[j + 2]), __uint_as_float(r0[j + 3]));
        #pragma unroll
        for (int j = 0; j < 32; j += 4)
            *(float4*)(cp + 32 + j) = make_float4(
                __uint_as_float(r1[j]), __uint_as_float(r1[j + 1]),
                __uint_as_float(r1[j + 2]), __uint_as_float(r1[j + 3]));
    }
    __syncthreads();
    if (wid == 0) {
        asm volatile("tcgen05.dealloc.cta_group::1.sync.aligned.b32 %0, %1;"
                     :: "r"(tmem), "r"(128u));
    }
#endif  // HAS_TCGEN05
}

extern "C" void kernel_launch(void* const* d_in, const int* in_sizes, int n_in,
                              void* d_out, int out_size)
{
    (void)in_sizes; (void)n_in; (void)out_size;
    const float* A = (const float*)d_in[0];
    float* out = (float*)d_out;

    float *b0 = nullptr, *b1 = nullptr;
    cudaGetSymbolAddress((void**)&b0, g_buf0);
    cudaGetSymbolAddress((void**)&b1, g_buf1);

    cudaFuncSetAttribute((const void*)tree_gemm<true>,
                         cudaFuncAttributeMaxDynamicSharedMemorySize, SM_TOTAL);
    cudaFuncSetAttribute((const void*)tree_gemm<false>,
                         cudaFuncAttributeMaxDynamicSharedMemorySize, SM_TOTAL);

    // Level 1: 1000 raw A -> 500 products (M formed on load)
    tree_gemm<true><<<dim3(4, 4, 500), 256, SM_TOTAL>>>(A, b0);

    int cnt = 500;
    float* src = b0;
    float* dst = b1;
    while (cnt > 1) {
        const int pairs = cnt >> 1;
        float* o = (cnt == 2) ? out : dst;
        tree_gemm<false><<<dim3(4, 4, pairs), 256, SM_TOTAL>>>(src, o);
        if (cnt & 1) {
            cudaMemcpyAsync(o + (size_t)pairs * DD,
                            src + (size_t)(cnt - 1) * DD,
                            DD * sizeof(float), cudaMemcpyDeviceToDevice);
        }
        cnt = pairs + (cnt & 1);
        float* t = src; src = dst; dst = t;
    }
}